// round 9
// baseline (speedup 1.0000x reference)
#include <cuda_runtime.h>
#include <cuda_bf16.h>
#include <mma.h>
#include <cstdint>

#define NN 50000
#define NE 800000
#define HID 128
#define LATD 64
#define IN_NODE 11
#define IN_EDGE 4
#define NB_SCAN 98   // ceil(50000/512)

// ---------------- device scratch ----------------
__device__ float g_h0buf[NN * HID];
__device__ float g_h1buf[NN * HID];
__device__ float g_agg[NN * HID];
__device__ float g_P1[NN * HID];
__device__ float g_P2[NN * HID];
__device__ float g_nf[NN * HID];
// counting-sort scratch
__device__ int g_cnt[NN];
__device__ int g_off[NB_SCAN * 512];
__device__ int g_cur[NN];
__device__ int g_blksum[NB_SCAN];
__device__ int g_blkoff[NB_SCAN];
// permuted (row-sorted) edge arrays
__device__ int   g_rowS[NE];
__device__ int   g_colS[NE];
__device__ float g_radS[NE];
__device__ float4 g_eaS[NE];
// bf16 hi/lo weight splits (pre/node GEMMs)
__device__ __nv_bfloat16 g_E1h[2][2][HID * HID];      // ew1 rows 0..255 as two [128][128]
__device__ __nv_bfloat16 g_E1l[2][2][HID * HID];
__device__ __nv_bfloat16 g_N1h[2][2 * HID * HID];     // [wsum ; W1b] [256][128]
__device__ __nv_bfloat16 g_N1l[2][2 * HID * HID];
__device__ __nv_bfloat16 g_N2h[2][HID * HID];         // nw2 [128][128]
__device__ __nv_bfloat16 g_N2l[2][HID * HID];

__device__ __forceinline__ float elu(float v) {
    return v > 0.f ? v : (__expf(v) - 1.f);
}

__device__ __forceinline__ void red4(float* p, float a, float b, float c, float d) {
    asm volatile("red.global.add.v4.f32 [%0], {%1,%2,%3,%4};"
                 :: "l"(p), "f"(a), "f"(b), "f"(c), "f"(d) : "memory");
}

__device__ __forceinline__ uint32_t pack_bf16(float e0, float e1) {
    uint32_t r;
    asm("cvt.rn.bf16x2.f32 %0, %1, %2;" : "=r"(r) : "f"(e1), "f"(e0));
    return r;
}

// ---------------- small kernels ----------------
__global__ void embed_kernel(const float* __restrict__ h0,
                             const float* __restrict__ emb_w,
                             const float* __restrict__ emb_b) {
    int idx = blockIdx.x * 256 + threadIdx.x;
    if (idx >= NN * HID) return;
    int n = idx >> 7, j = idx & 127;
    float acc = emb_b[j];
#pragma unroll
    for (int k = 0; k < IN_NODE; k++)
        acc += h0[n * IN_NODE + k] * emb_w[k * HID + j];
    g_h0buf[idx] = acc;
}

__global__ void zero_agg_kernel() {
    int i = blockIdx.x * 256 + threadIdx.x;
    if (i < NN * HID / 4)
        ((float4*)g_agg)[i] = make_float4(0.f, 0.f, 0.f, 0.f);
}

// split ew1 (rows 0..255), node W1 (wsum-folded), node W2 into bf16 hi/lo
__global__ void prep_split_kernel(const float* __restrict__ ew1,
                                  const float* __restrict__ nw1,
                                  const float* __restrict__ nw2) {
    int idx = blockIdx.x * 256 + threadIdx.x;
    if (idx >= 163840) return;
    float v;
    __nv_bfloat16 *dh, *dl;
    if (idx < 65536) {
        int l = idx >> 15, rest = idx & 32767;
        int y = rest >> 14, r2 = rest & 16383;
        v = ew1[(l * 261 + y * 128 + (r2 >> 7)) * 128 + (r2 & 127)];
        dh = &g_E1h[l][y][r2];
        dl = &g_E1l[l][y][r2];
    } else if (idx < 131072) {
        int t = idx - 65536;
        int l = t >> 15, rest = t & 32767;
        int k = rest >> 7, j = rest & 127;
        if (k < 128)
            v = nw1[(l * 384 + k) * 128 + j] + nw1[(l * 384 + 256 + k) * 128 + j];
        else
            v = nw1[(l * 384 + 128 + (k - 128)) * 128 + j];
        dh = &g_N1h[l][rest];
        dl = &g_N1l[l][rest];
    } else {
        int t = idx - 131072;
        int l = t >> 14, rest = t & 16383;
        v = nw2[l * 16384 + rest];
        dh = &g_N2h[l][rest];
        dl = &g_N2l[l][rest];
    }
    __nv_bfloat16 hb = __float2bfloat16(v);
    *dh = hb;
    *dl = __float2bfloat16(v - __bfloat162float(hb));
}

// ---------------- counting sort of edges by row ----------------
__global__ void sort_zero_kernel() {
    int i = blockIdx.x * 256 + threadIdx.x;
    if (i < NN) g_cnt[i] = 0;
}

__global__ void sort_hist_kernel(const int* __restrict__ row) {
    int e = blockIdx.x * 256 + threadIdx.x;
    if (e < NE) atomicAdd(&g_cnt[row[e]], 1);
}

__global__ void sort_scan1_kernel() {
    __shared__ int buf[512];
    int t = threadIdx.x;
    int i = blockIdx.x * 512 + t;
    int v = (i < NN) ? g_cnt[i] : 0;
    buf[t] = v;
    __syncthreads();
#pragma unroll
    for (int d = 1; d < 512; d <<= 1) {
        int x = (t >= d) ? buf[t - d] : 0;
        __syncthreads();
        buf[t] += x;
        __syncthreads();
    }
    g_off[i] = buf[t] - v;
    if (t == 511) g_blksum[blockIdx.x] = buf[511];
}

__global__ void sort_scan2_kernel() {
    if (threadIdx.x == 0) {
        int s = 0;
        for (int k = 0; k < NB_SCAN; k++) {
            g_blkoff[k] = s;
            s += g_blksum[k];
        }
    }
}

__global__ void sort_scan3_kernel() {
    int i = blockIdx.x * 256 + threadIdx.x;
    if (i < NN) {
        int o = g_off[i] + g_blkoff[i >> 9];
        g_off[i] = o;
        g_cur[i] = o;
    }
}

__global__ void sort_scatter_kernel(const int* __restrict__ row,
                                    const int* __restrict__ col,
                                    const float* __restrict__ x,
                                    const float* __restrict__ edge_attr) {
    int e = blockIdx.x * 256 + threadIdx.x;
    if (e >= NE) return;
    int r = row[e], c = col[e];
    float dx = x[r * 3 + 0] - x[c * 3 + 0];
    float dy = x[r * 3 + 1] - x[c * 3 + 1];
    float dz = x[r * 3 + 2] - x[c * 3 + 2];
    float rad = dx * dx + dy * dy + dz * dz;
    int pos = atomicAdd(&g_cur[r], 1);
    g_rowS[pos] = r;
    g_colS[pos] = c;
    g_radS[pos] = rad;
    g_eaS[pos] = *(const float4*)(edge_attr + (size_t)e * 4);
}

// ---------------- generic dense GEMM (bf16 3-pass): out[M,128] = act(A@B + bias) ----------------
// blockIdx.y == 1 switches to (Bh2/Bl2, out2) — fuses the P1/P2 pair into one launch.
static constexpr int GA_ST = 72;
static constexpr int GB_ST = 136;
static constexpr int GD_ST = 132;
static constexpr int G_SAH = 0;
static constexpr int G_SAL = 18432;
static constexpr int G_SBH = 36864;
static constexpr int G_SBL = 54272;
static constexpr int GEMM_SMEM = 71680;

__global__ void __launch_bounds__(256, 2)
gemm_wmma_kernel(const float* __restrict__ A0, const float* __restrict__ A1,
                 int k64,
                 const __nv_bfloat16* __restrict__ Bh,
                 const __nv_bfloat16* __restrict__ Bl,
                 const float* __restrict__ bias,
                 float* __restrict__ out, int do_elu,
                 const __nv_bfloat16* Bh2, const __nv_bfloat16* Bl2, float* out2) {
    extern __shared__ char smem[];
    __nv_bfloat16* sAh = (__nv_bfloat16*)(smem + G_SAH);
    __nv_bfloat16* sAl = (__nv_bfloat16*)(smem + G_SAL);
    __nv_bfloat16* sBh = (__nv_bfloat16*)(smem + G_SBH);
    __nv_bfloat16* sBl = (__nv_bfloat16*)(smem + G_SBL);
    float* sD = (float*)smem;

    if (blockIdx.y == 1) { Bh = Bh2; Bl = Bl2; out = out2; }

    int tid = threadIdx.x;
    int wid = tid >> 5;
    int n0 = blockIdx.x * 128;
    int r = tid >> 1, hf = tid & 1;
    int n = n0 + r;

    using namespace nvcuda::wmma;
    fragment<accumulator, 16, 16, 16, float> acc[8];
#pragma unroll
    for (int j = 0; j < 8; j++) fill_fragment(acc[j], 0.f);

    for (int c = 0; c < k64; c++) {
        {
            const float* src = (c < 2) ? A0 : A1;
            int kbase = (c & 1) * 64;
            if (n < NN) {
#pragma unroll
                for (int q = 0; q < 8; q++) {
                    int col = hf * 32 + q * 4;
                    float4 v = *(const float4*)(src + (size_t)n * HID + kbase + col);
                    float h0f = __bfloat162float(__float2bfloat16(v.x));
                    float h1f = __bfloat162float(__float2bfloat16(v.y));
                    float h2f = __bfloat162float(__float2bfloat16(v.z));
                    float h3f = __bfloat162float(__float2bfloat16(v.w));
                    uint32_t* ph = (uint32_t*)(sAh + r * GA_ST + col);
                    uint32_t* pl = (uint32_t*)(sAl + r * GA_ST + col);
                    ph[0] = pack_bf16(h0f, h1f);
                    ph[1] = pack_bf16(h2f, h3f);
                    pl[0] = pack_bf16(v.x - h0f, v.y - h1f);
                    pl[1] = pack_bf16(v.z - h2f, v.w - h3f);
                }
            } else {
#pragma unroll
                for (int q = 0; q < 8; q++) {
                    int col = hf * 32 + q * 4;
                    uint32_t* ph = (uint32_t*)(sAh + r * GA_ST + col);
                    uint32_t* pl = (uint32_t*)(sAl + r * GA_ST + col);
                    ph[0] = 0; ph[1] = 0; pl[0] = 0; pl[1] = 0;
                }
            }
        }
        {
#pragma unroll
            for (int it = 0; it < 4; it++) {
                int i = tid + it * 256;
                int kb = i >> 4, u = i & 15;
                *(uint4*)(sBh + kb * GB_ST + u * 8) =
                    *(const uint4*)(Bh + (size_t)(c * 64 + kb) * HID + u * 8);
                *(uint4*)(sBl + kb * GB_ST + u * 8) =
                    *(const uint4*)(Bl + (size_t)(c * 64 + kb) * HID + u * 8);
            }
        }
        __syncthreads();

        {
            int m0 = wid * 16;
#pragma unroll
            for (int kf = 0; kf < 4; kf++) {
                fragment<matrix_a, 16, 16, 16, __nv_bfloat16, row_major> ah, al;
                load_matrix_sync(ah, sAh + m0 * GA_ST + kf * 16, GA_ST);
                load_matrix_sync(al, sAl + m0 * GA_ST + kf * 16, GA_ST);
#pragma unroll
                for (int nf = 0; nf < 8; nf++) {
                    fragment<matrix_b, 16, 16, 16, __nv_bfloat16, row_major> b;
                    load_matrix_sync(b, sBh + (kf * 16) * GB_ST + nf * 16, GB_ST);
                    mma_sync(acc[nf], ah, b, acc[nf]);
                    mma_sync(acc[nf], al, b, acc[nf]);
                }
            }
#pragma unroll
            for (int kf = 0; kf < 4; kf++) {
                fragment<matrix_a, 16, 16, 16, __nv_bfloat16, row_major> ah;
                load_matrix_sync(ah, sAh + m0 * GA_ST + kf * 16, GA_ST);
#pragma unroll
                for (int nf = 0; nf < 8; nf++) {
                    fragment<matrix_b, 16, 16, 16, __nv_bfloat16, row_major> b;
                    load_matrix_sync(b, sBl + (kf * 16) * GB_ST + nf * 16, GB_ST);
                    mma_sync(acc[nf], ah, b, acc[nf]);
                }
            }
        }
        __syncthreads();
    }

    {
        int m0 = wid * 16;
#pragma unroll
        for (int nf = 0; nf < 8; nf++)
            store_matrix_sync(sD + m0 * GD_ST + nf * 16, acc[nf], GD_ST, mem_row_major);
    }
    __syncthreads();

    if (n < NN) {
#pragma unroll
        for (int q = 0; q < 16; q++) {
            int col = hf * 64 + q * 4;
            float4 v = *(const float4*)(sD + r * GD_ST + col);
            if (bias) {
                v.x += bias[col + 0];
                v.y += bias[col + 1];
                v.z += bias[col + 2];
                v.w += bias[col + 3];
            }
            if (do_elu) {
                v.x = elu(v.x); v.y = elu(v.y); v.z = elu(v.z); v.w = elu(v.w);
            }
            *(float4*)(out + (size_t)n * HID + col) = v;
        }
    }
}

// ---------------- edge kernel: R7 structure, single-pass TF32 MMA ----------------
static constexpr int AST = 132;   // f32 stride, A tile
static constexpr int BST = 68;    // f32 stride, B chunk (and D chunk)
static constexpr int SM_A  = 0;        // 128*132*4 = 67584
static constexpr int SM_B  = 67584;    // 128*68*4 = 34816; D unions here after MMA
static constexpr int SM_WT = 102400;   // 5*128*4 = 2560
static constexpr int SM_B1 = 104960;   // 512
static constexpr int SM_B2 = 105472;   // 512
static constexpr int SM_ROW = 105984;  // 512
static constexpr int EDGE_SMEM_BYTES = 106496;

__global__ void __launch_bounds__(256, 2)
edge_tf32_kernel(const float* __restrict__ ew1, const float* __restrict__ eb1,
                 const float* __restrict__ ew2, const float* __restrict__ eb2, int layer) {
    extern __shared__ char smem[];
    float* sA  = (float*)(smem + SM_A);
    float* sB  = (float*)(smem + SM_B);
    float* sD  = (float*)(smem + SM_B);   // union with B (after MMA)
    float* sWT = (float*)(smem + SM_WT);
    float* sB1 = (float*)(smem + SM_B1);
    float* sB2 = (float*)(smem + SM_B2);
    int*   sRow = (int*)(smem + SM_ROW);

    int tid = threadIdx.x;
    int wid = tid >> 5;
    int e0 = blockIdx.x * 128;

    // stage tail weights, biases, sorted rows
    for (int i = tid; i < 5 * HID; i += 256) sWT[i] = ew1[(layer * 261 + 2 * HID) * HID + i];
    if (tid < HID) {
        sB1[tid] = eb1[layer * HID + tid];
        sB2[tid] = eb2[layer * HID + tid];
    }
    if (tid < 128) sRow[tid] = g_rowS[e0 + tid];
    __syncthreads();

    // A-build: elu(P1[row]+P2[col]+rad*w+ea@Wtail+b1) -> fp32 SMEM (no split needed for tf32)
    {
        int m = tid >> 1, hf = tid & 1;
        int e = e0 + m;
        int r = sRow[m], c = g_colS[e];
        float rad = g_radS[e];
        float4 ea = g_eaS[e];
        const float* p1r = g_P1 + (size_t)r * HID;
        const float* p2r = g_P2 + (size_t)c * HID;
#pragma unroll
        for (int q = 0; q < 16; q++) {
            int jb = hf * 64 + q * 4;
            float4 p1 = *(const float4*)(p1r + jb);
            float4 p2 = *(const float4*)(p2r + jb);
            float4 w0 = *(const float4*)(sWT + 0 * HID + jb);
            float4 w1 = *(const float4*)(sWT + 1 * HID + jb);
            float4 w2 = *(const float4*)(sWT + 2 * HID + jb);
            float4 w3 = *(const float4*)(sWT + 3 * HID + jb);
            float4 w4 = *(const float4*)(sWT + 4 * HID + jb);
            float4 bb = *(const float4*)(sB1 + jb);
            float4 o;
            o.x = elu(p1.x + p2.x + rad * w0.x + ea.x * w1.x + ea.y * w2.x + ea.z * w3.x + ea.w * w4.x + bb.x);
            o.y = elu(p1.y + p2.y + rad * w0.y + ea.x * w1.y + ea.y * w2.y + ea.z * w3.y + ea.w * w4.y + bb.y);
            o.z = elu(p1.z + p2.z + rad * w0.z + ea.x * w1.z + ea.y * w2.z + ea.z * w3.z + ea.w * w4.z + bb.z);
            o.w = elu(p1.w + p2.w + rad * w0.w + ea.x * w1.w + ea.y * w2.w + ea.z * w3.w + ea.w * w4.w + bb.w);
            *(float4*)(sA + m * AST + jb) = o;
        }
    }
    __syncthreads();

    using namespace nvcuda::wmma;
    const float* W2 = ew2 + (size_t)layer * HID * HID;

#pragma unroll
    for (int nc = 0; nc < 2; nc++) {
        // stage B chunk: [128 k][64 n] fp32, stride 68
        {
#pragma unroll
            for (int it = 0; it < 8; it++) {
                int i = tid + it * 256;
                int k = i >> 4, u = i & 15;
                *(float4*)(sB + k * BST + u * 4) =
                    *(const float4*)(W2 + (size_t)k * HID + nc * 64 + u * 4);
            }
        }
        __syncthreads();

        // tf32 MMA: warp wid -> rows [wid*16, +16), all 64 chunk cols
        {
            int m0 = wid * 16;
            fragment<accumulator, 16, 16, 8, float> acc[4];
#pragma unroll
            for (int j = 0; j < 4; j++) fill_fragment(acc[j], 0.f);

#pragma unroll
            for (int k = 0; k < 16; k++) {
                fragment<matrix_a, 16, 16, 8, precision::tf32, row_major> a;
                load_matrix_sync(a, sA + m0 * AST + k * 8, AST);
#pragma unroll
                for (int t = 0; t < a.num_elements; t++)
                    a.x[t] = __float_to_tf32(a.x[t]);
#pragma unroll
                for (int nt = 0; nt < 4; nt++) {
                    fragment<matrix_b, 16, 16, 8, precision::tf32, row_major> b;
                    load_matrix_sync(b, sB + (k * 8) * BST + nt * 16, BST);
#pragma unroll
                    for (int t = 0; t < b.num_elements; t++)
                        b.x[t] = __float_to_tf32(b.x[t]);
                    mma_sync(acc[nt], a, b, acc[nt]);
                }
            }

            __syncthreads();  // B chunk dead before D overwrites it
#pragma unroll
            for (int nt = 0; nt < 4; nt++)
                store_matrix_sync(sD + m0 * BST + nt * 16, acc[nt], BST, mem_row_major);
        }
        __syncthreads();

        // segmented scatter: eg = 8-edge group, ct = 4-col group
        {
            int ct = tid & 15, eg = tid >> 4;
            int jb = ct * 4;
            float b0 = sB2[nc * 64 + jb + 0];
            float b1v = sB2[nc * 64 + jb + 1];
            float b2v = sB2[nc * 64 + jb + 2];
            float b3v = sB2[nc * 64 + jb + 3];
            float r0 = 0.f, r1 = 0.f, r2 = 0.f, r3 = 0.f;
            int cur = sRow[eg * 8];
#pragma unroll
            for (int i = 0; i < 8; i++) {
                int m = eg * 8 + i;
                int rr = sRow[m];
                if (rr != cur) {
                    red4(g_agg + (size_t)cur * HID + nc * 64 + jb, r0, r1, r2, r3);
                    r0 = r1 = r2 = r3 = 0.f;
                    cur = rr;
                }
                const float* sd = sD + m * BST + jb;
                r0 += elu(sd[0] + b0);
                r1 += elu(sd[1] + b1v);
                r2 += elu(sd[2] + b2v);
                r3 += elu(sd[3] + b3v);
            }
            red4(g_agg + (size_t)cur * HID + nc * 64 + jb, r0, r1, r2, r3);
        }
        __syncthreads();  // D dead before next chunk stages B
    }
}

// ---------------- final head ----------------
__global__ void final_kernel(const float* __restrict__ label,
                             const float* __restrict__ eps,
                             const float* __restrict__ mu_w, const float* __restrict__ mu_b,
                             const float* __restrict__ var_w, const float* __restrict__ var_b,
                             float* __restrict__ out) {
    int idx = blockIdx.x * 256 + threadIdx.x;
    if (idx >= NN * LATD) return;
    int n = idx >> 6, l = idx & 63;
    float am = mu_b[l], av = var_b[l];
    const float* hrow = g_h0buf + n * HID;
#pragma unroll 4
    for (int k = 0; k < HID; k++) {
        float hv = hrow[k];
        am += hv * mu_w[k * LATD + l];
        av += hv * var_w[k * LATD + l];
    }
#pragma unroll
    for (int c = 0; c < 7; c++) {
        float lv = label[n * 7 + c];
        am += lv * mu_w[(HID + c) * LATD + l];
        av += lv * var_w[(HID + c) * LATD + l];
    }
    out[idx] = am + 0.01f * eps[idx] * __expf(0.5f * av);
}

// ---------------- launch ----------------
extern "C" void kernel_launch(void* const* d_in, const int* in_sizes, int n_in,
                              void* d_out, int out_size) {
    const float* h0        = (const float*)d_in[0];
    const float* label     = (const float*)d_in[1];
    const float* x         = (const float*)d_in[2];
    const float* edge_attr = (const float*)d_in[3];
    const float* eps       = (const float*)d_in[4];
    const float* emb_w     = (const float*)d_in[5];
    const float* emb_b     = (const float*)d_in[6];
    const float* ew1       = (const float*)d_in[7];
    const float* eb1       = (const float*)d_in[8];
    const float* ew2       = (const float*)d_in[9];
    const float* eb2       = (const float*)d_in[10];
    const float* nw1       = (const float*)d_in[11];
    const float* nb1       = (const float*)d_in[12];
    const float* nw2       = (const float*)d_in[13];
    const float* nb2       = (const float*)d_in[14];
    const float* mu_w      = (const float*)d_in[15];
    const float* mu_b      = (const float*)d_in[16];
    const float* var_w     = (const float*)d_in[17];
    const float* var_b     = (const float*)d_in[18];
    const int*   edges     = (const int*)d_in[19];
    const int* rowp = edges;
    const int* colp = edges + NE;
    float* out = (float*)d_out;

    cudaFuncSetAttribute(edge_tf32_kernel, cudaFuncAttributeMaxDynamicSharedMemorySize, EDGE_SMEM_BYTES);
    cudaFuncSetAttribute(gemm_wmma_kernel, cudaFuncAttributeMaxDynamicSharedMemorySize, GEMM_SMEM);

    const int GGRID = (NN + 127) / 128;   // 391

    embed_kernel<<<(NN * HID + 255) / 256, 256>>>(h0, emb_w, emb_b);
    prep_split_kernel<<<(163840 + 255) / 256, 256>>>(ew1, nw1, nw2);

    // counting sort of edges by source node (once per launch)
    sort_zero_kernel<<<(NN + 255) / 256, 256>>>();
    sort_hist_kernel<<<(NE + 255) / 256, 256>>>(rowp);
    sort_scan1_kernel<<<NB_SCAN, 512>>>();
    sort_scan2_kernel<<<1, 32>>>();
    sort_scan3_kernel<<<(NN + 255) / 256, 256>>>();
    sort_scatter_kernel<<<(NE + 255) / 256, 256>>>(rowp, colp, x, edge_attr);

    float *h0p, *h1p, *p1p, *p2p, *aggp, *nfp;
    cudaGetSymbolAddress((void**)&h0p, g_h0buf);
    cudaGetSymbolAddress((void**)&h1p, g_h1buf);
    cudaGetSymbolAddress((void**)&p1p, g_P1);
    cudaGetSymbolAddress((void**)&p2p, g_P2);
    cudaGetSymbolAddress((void**)&aggp, g_agg);
    cudaGetSymbolAddress((void**)&nfp, g_nf);
    __nv_bfloat16 *e1h, *e1l, *n1h, *n1l, *n2h, *n2l;
    cudaGetSymbolAddress((void**)&e1h, g_E1h);
    cudaGetSymbolAddress((void**)&e1l, g_E1l);
    cudaGetSymbolAddress((void**)&n1h, g_N1h);
    cudaGetSymbolAddress((void**)&n1l, g_N1l);
    cudaGetSymbolAddress((void**)&n2h, g_N2h);
    cudaGetSymbolAddress((void**)&n2l, g_N2l);

    for (int layer = 0; layer < 2; layer++) {
        float* hsrc_p = (layer == 0) ? h0p : h1p;
        float* hdst   = (layer == 0) ? h1p : h0p;

        zero_agg_kernel<<<(NN * HID / 4 + 255) / 256, 256>>>();

        // P1 and P2 in one launch (gridDim.y = 2)
        gemm_wmma_kernel<<<dim3(GGRID, 2), 256, GEMM_SMEM>>>(
            hsrc_p, nullptr, 2,
            e1h + (size_t)layer * 2 * HID * HID, e1l + (size_t)layer * 2 * HID * HID,
            nullptr, p1p, 0,
            e1h + ((size_t)layer * 2 + 1) * HID * HID,
            e1l + ((size_t)layer * 2 + 1) * HID * HID, p2p);

        edge_tf32_kernel<<<NE / 128, 256, EDGE_SMEM_BYTES>>>(ew1, eb1, ew2, eb2, layer);

        // node GEMM1: nf = elu([h|agg] @ N1 + nb1)
        gemm_wmma_kernel<<<dim3(GGRID, 1), 256, GEMM_SMEM>>>(
            hsrc_p, aggp, 4,
            n1h + (size_t)layer * 2 * HID * HID, n1l + (size_t)layer * 2 * HID * HID,
            nb1 + layer * HID, nfp, 1, nullptr, nullptr, nullptr);
        // node GEMM2: hdst = nf @ N2 + nb2
        gemm_wmma_kernel<<<dim3(GGRID, 1), 256, GEMM_SMEM>>>(
            nfp, nullptr, 2,
            n2h + (size_t)layer * HID * HID, n2l + (size_t)layer * HID * HID,
            nb2 + layer * HID, hdst, 0, nullptr, nullptr, nullptr);
    }

    final_kernel<<<(NN * LATD + 255) / 256, 256>>>(label, eps, mu_w, mu_b,
                                                   var_w, var_b, out);
}

// round 10
// speedup vs baseline: 1.1553x; 1.1553x over previous
#include <cuda_runtime.h>
#include <cuda_bf16.h>
#include <mma.h>
#include <cstdint>

#define NN 50000
#define NE 800000
#define HID 128
#define LATD 64
#define IN_NODE 11
#define IN_EDGE 4
#define NB_SCAN 98   // ceil(50000/512)

// ---------------- device scratch ----------------
__device__ float g_h0buf[NN * HID];
__device__ float g_h1buf[NN * HID];
__device__ float g_agg[NN * HID];
__device__ float g_P1[NN * HID];
__device__ float g_P2[NN * HID];
__device__ float g_nf[NN * HID];
// counting-sort scratch
__device__ int g_cnt[NN];
__device__ int g_off[NB_SCAN * 512];
__device__ int g_cur[NN];
__device__ int g_blksum[NB_SCAN];
__device__ int g_blkoff[NB_SCAN];
// permuted (row-sorted) edge arrays
__device__ int   g_rowS[NE];
__device__ int   g_colS[NE];
__device__ float g_radS[NE];
__device__ float4 g_eaS[NE];
// bf16 hi/lo weight splits
__device__ __nv_bfloat16 g_Bh[2][HID * HID];          // edge W2 [K][N]
__device__ __nv_bfloat16 g_Bl[2][HID * HID];
__device__ __nv_bfloat16 g_E1h[2][2][HID * HID];      // ew1 rows 0..255 as two [128][128]
__device__ __nv_bfloat16 g_E1l[2][2][HID * HID];
__device__ __nv_bfloat16 g_N1h[2][2 * HID * HID];     // [wsum ; W1b] [256][128]
__device__ __nv_bfloat16 g_N1l[2][2 * HID * HID];
__device__ __nv_bfloat16 g_N2h[2][HID * HID];         // nw2 [128][128]
__device__ __nv_bfloat16 g_N2l[2][HID * HID];

__device__ __forceinline__ float elu(float v) {
    return v > 0.f ? v : (__expf(v) - 1.f);
}

__device__ __forceinline__ void red4(float* p, float a, float b, float c, float d) {
    asm volatile("red.global.add.v4.f32 [%0], {%1,%2,%3,%4};"
                 :: "l"(p), "f"(a), "f"(b), "f"(c), "f"(d) : "memory");
}

__device__ __forceinline__ uint32_t pack_bf16(float e0, float e1) {
    uint32_t r;
    asm("cvt.rn.bf16x2.f32 %0, %1, %2;" : "=r"(r) : "f"(e1), "f"(e0));
    return r;
}

// cp.async helpers (16B)
__device__ __forceinline__ void cp16(void* smem_dst, const void* gsrc) {
    uint32_t d = (uint32_t)__cvta_generic_to_shared(smem_dst);
    asm volatile("cp.async.ca.shared.global [%0], [%1], 16;" :: "r"(d), "l"(gsrc) : "memory");
}
#define CP_COMMIT() asm volatile("cp.async.commit_group;" ::: "memory")
#define CP_WAIT0()  asm volatile("cp.async.wait_group 0;" ::: "memory")

// ---------------- small kernels ----------------
__global__ void embed_kernel(const float* __restrict__ h0,
                             const float* __restrict__ emb_w,
                             const float* __restrict__ emb_b) {
    int idx = blockIdx.x * 256 + threadIdx.x;
    if (idx >= NN * HID) return;
    int n = idx >> 7, j = idx & 127;
    float acc = emb_b[j];
#pragma unroll
    for (int k = 0; k < IN_NODE; k++)
        acc += h0[n * IN_NODE + k] * emb_w[k * HID + j];
    g_h0buf[idx] = acc;
}

__global__ void zero_agg_kernel() {
    int i = blockIdx.x * 256 + threadIdx.x;
    if (i < NN * HID / 4)
        ((float4*)g_agg)[i] = make_float4(0.f, 0.f, 0.f, 0.f);
}

// split edge W2 into bf16 hi/lo, layout [K][N]
__global__ void w2prep_kernel(const float* __restrict__ ew2) {
    int idx = blockIdx.x * 256 + threadIdx.x;
    if (idx >= 2 * HID * HID) return;
    int layer = idx >> 14;
    int rem = idx & 16383;
    float v = ew2[layer * HID * HID + rem];
    __nv_bfloat16 hb = __float2bfloat16(v);
    g_Bh[layer][rem] = hb;
    g_Bl[layer][rem] = __float2bfloat16(v - __bfloat162float(hb));
}

// split ew1 (rows 0..255), node W1 (wsum-folded), node W2 into bf16 hi/lo
__global__ void prep_split_kernel(const float* __restrict__ ew1,
                                  const float* __restrict__ nw1,
                                  const float* __restrict__ nw2) {
    int idx = blockIdx.x * 256 + threadIdx.x;
    if (idx >= 163840) return;
    float v;
    __nv_bfloat16 *dh, *dl;
    if (idx < 65536) {
        int l = idx >> 15, rest = idx & 32767;
        int y = rest >> 14, r2 = rest & 16383;
        v = ew1[(l * 261 + y * 128 + (r2 >> 7)) * 128 + (r2 & 127)];
        dh = &g_E1h[l][y][r2];
        dl = &g_E1l[l][y][r2];
    } else if (idx < 131072) {
        int t = idx - 65536;
        int l = t >> 15, rest = t & 32767;
        int k = rest >> 7, j = rest & 127;
        if (k < 128)
            v = nw1[(l * 384 + k) * 128 + j] + nw1[(l * 384 + 256 + k) * 128 + j];
        else
            v = nw1[(l * 384 + 128 + (k - 128)) * 128 + j];
        dh = &g_N1h[l][rest];
        dl = &g_N1l[l][rest];
    } else {
        int t = idx - 131072;
        int l = t >> 14, rest = t & 16383;
        v = nw2[l * 16384 + rest];
        dh = &g_N2h[l][rest];
        dl = &g_N2l[l][rest];
    }
    __nv_bfloat16 hb = __float2bfloat16(v);
    *dh = hb;
    *dl = __float2bfloat16(v - __bfloat162float(hb));
}

// ---------------- counting sort of edges by row ----------------
__global__ void sort_zero_kernel() {
    int i = blockIdx.x * 256 + threadIdx.x;
    if (i < NN) g_cnt[i] = 0;
}

__global__ void sort_hist_kernel(const int* __restrict__ row) {
    int e = blockIdx.x * 256 + threadIdx.x;
    if (e < NE) atomicAdd(&g_cnt[row[e]], 1);
}

__global__ void sort_scan1_kernel() {
    __shared__ int buf[512];
    int t = threadIdx.x;
    int i = blockIdx.x * 512 + t;
    int v = (i < NN) ? g_cnt[i] : 0;
    buf[t] = v;
    __syncthreads();
#pragma unroll
    for (int d = 1; d < 512; d <<= 1) {
        int x = (t >= d) ? buf[t - d] : 0;
        __syncthreads();
        buf[t] += x;
        __syncthreads();
    }
    g_off[i] = buf[t] - v;
    if (t == 511) g_blksum[blockIdx.x] = buf[511];
}

__global__ void sort_scan2_kernel() {
    if (threadIdx.x == 0) {
        int s = 0;
        for (int k = 0; k < NB_SCAN; k++) {
            g_blkoff[k] = s;
            s += g_blksum[k];
        }
    }
}

__global__ void sort_scan3_kernel() {
    int i = blockIdx.x * 256 + threadIdx.x;
    if (i < NN) {
        int o = g_off[i] + g_blkoff[i >> 9];
        g_off[i] = o;
        g_cur[i] = o;
    }
}

__global__ void sort_scatter_kernel(const int* __restrict__ row,
                                    const int* __restrict__ col,
                                    const float* __restrict__ x,
                                    const float* __restrict__ edge_attr) {
    int e = blockIdx.x * 256 + threadIdx.x;
    if (e >= NE) return;
    int r = row[e], c = col[e];
    float dx = x[r * 3 + 0] - x[c * 3 + 0];
    float dy = x[r * 3 + 1] - x[c * 3 + 1];
    float dz = x[r * 3 + 2] - x[c * 3 + 2];
    float rad = dx * dx + dy * dy + dz * dz;
    int pos = atomicAdd(&g_cur[r], 1);
    g_rowS[pos] = r;
    g_colS[pos] = c;
    g_radS[pos] = rad;
    g_eaS[pos] = *(const float4*)(edge_attr + (size_t)e * 4);
}

// ---------------- generic dense GEMM (bf16 3-pass): out[M,128] = act(A@B + bias) ----------------
static constexpr int GA_ST = 72;
static constexpr int GB_ST = 136;
static constexpr int GD_ST = 132;
static constexpr int G_SAH = 0;
static constexpr int G_SAL = 18432;
static constexpr int G_SBH = 36864;
static constexpr int G_SBL = 54272;
static constexpr int GEMM_SMEM = 71680;

__global__ void __launch_bounds__(256, 2)
gemm_wmma_kernel(const float* __restrict__ A0, const float* __restrict__ A1,
                 int k64,
                 const __nv_bfloat16* __restrict__ Bh,
                 const __nv_bfloat16* __restrict__ Bl,
                 const float* __restrict__ bias,
                 float* __restrict__ out, int do_elu,
                 const __nv_bfloat16* Bh2, const __nv_bfloat16* Bl2, float* out2) {
    extern __shared__ char smem[];
    __nv_bfloat16* sAh = (__nv_bfloat16*)(smem + G_SAH);
    __nv_bfloat16* sAl = (__nv_bfloat16*)(smem + G_SAL);
    __nv_bfloat16* sBh = (__nv_bfloat16*)(smem + G_SBH);
    __nv_bfloat16* sBl = (__nv_bfloat16*)(smem + G_SBL);
    float* sD = (float*)smem;

    if (blockIdx.y == 1) { Bh = Bh2; Bl = Bl2; out = out2; }

    int tid = threadIdx.x;
    int wid = tid >> 5;
    int n0 = blockIdx.x * 128;
    int r = tid >> 1, hf = tid & 1;
    int n = n0 + r;

    using namespace nvcuda::wmma;
    fragment<accumulator, 16, 16, 16, float> acc[8];
#pragma unroll
    for (int j = 0; j < 8; j++) fill_fragment(acc[j], 0.f);

    for (int c = 0; c < k64; c++) {
        // issue B chunk staging as cp.async (overlaps with A split/pack below)
        {
#pragma unroll
            for (int it = 0; it < 4; it++) {
                int i = tid + it * 256;
                int kb = i >> 4, u = i & 15;
                cp16(sBh + kb * GB_ST + u * 8, Bh + (size_t)(c * 64 + kb) * HID + u * 8);
                cp16(sBl + kb * GB_ST + u * 8, Bl + (size_t)(c * 64 + kb) * HID + u * 8);
            }
            CP_COMMIT();
        }
        // stage A chunk: fp32 -> bf16 hi/lo (compute-heavy; hides the cp.async)
        {
            const float* src = (c < 2) ? A0 : A1;
            int kbase = (c & 1) * 64;
            if (n < NN) {
#pragma unroll
                for (int q = 0; q < 8; q++) {
                    int col = hf * 32 + q * 4;
                    float4 v = *(const float4*)(src + (size_t)n * HID + kbase + col);
                    float h0f = __bfloat162float(__float2bfloat16(v.x));
                    float h1f = __bfloat162float(__float2bfloat16(v.y));
                    float h2f = __bfloat162float(__float2bfloat16(v.z));
                    float h3f = __bfloat162float(__float2bfloat16(v.w));
                    uint32_t* ph = (uint32_t*)(sAh + r * GA_ST + col);
                    uint32_t* pl = (uint32_t*)(sAl + r * GA_ST + col);
                    ph[0] = pack_bf16(h0f, h1f);
                    ph[1] = pack_bf16(h2f, h3f);
                    pl[0] = pack_bf16(v.x - h0f, v.y - h1f);
                    pl[1] = pack_bf16(v.z - h2f, v.w - h3f);
                }
            } else {
#pragma unroll
                for (int q = 0; q < 8; q++) {
                    int col = hf * 32 + q * 4;
                    uint32_t* ph = (uint32_t*)(sAh + r * GA_ST + col);
                    uint32_t* pl = (uint32_t*)(sAl + r * GA_ST + col);
                    ph[0] = 0; ph[1] = 0; pl[0] = 0; pl[1] = 0;
                }
            }
        }
        CP_WAIT0();
        __syncthreads();

        {
            int m0 = wid * 16;
#pragma unroll
            for (int kf = 0; kf < 4; kf++) {
                fragment<matrix_a, 16, 16, 16, __nv_bfloat16, row_major> ah, al;
                load_matrix_sync(ah, sAh + m0 * GA_ST + kf * 16, GA_ST);
                load_matrix_sync(al, sAl + m0 * GA_ST + kf * 16, GA_ST);
#pragma unroll
                for (int nf = 0; nf < 8; nf++) {
                    fragment<matrix_b, 16, 16, 16, __nv_bfloat16, row_major> b;
                    load_matrix_sync(b, sBh + (kf * 16) * GB_ST + nf * 16, GB_ST);
                    mma_sync(acc[nf], ah, b, acc[nf]);
                    mma_sync(acc[nf], al, b, acc[nf]);
                }
            }
#pragma unroll
            for (int kf = 0; kf < 4; kf++) {
                fragment<matrix_a, 16, 16, 16, __nv_bfloat16, row_major> ah;
                load_matrix_sync(ah, sAh + m0 * GA_ST + kf * 16, GA_ST);
#pragma unroll
                for (int nf = 0; nf < 8; nf++) {
                    fragment<matrix_b, 16, 16, 16, __nv_bfloat16, row_major> b;
                    load_matrix_sync(b, sBl + (kf * 16) * GB_ST + nf * 16, GB_ST);
                    mma_sync(acc[nf], ah, b, acc[nf]);
                }
            }
        }
        __syncthreads();
    }

    {
        int m0 = wid * 16;
#pragma unroll
        for (int nf = 0; nf < 8; nf++)
            store_matrix_sync(sD + m0 * GD_ST + nf * 16, acc[nf], GD_ST, mem_row_major);
    }
    __syncthreads();

    if (n < NN) {
#pragma unroll
        for (int q = 0; q < 16; q++) {
            int col = hf * 64 + q * 4;
            float4 v = *(const float4*)(sD + r * GD_ST + col);
            if (bias) {
                v.x += bias[col + 0];
                v.y += bias[col + 1];
                v.z += bias[col + 2];
                v.w += bias[col + 3];
            }
            if (do_elu) {
                v.x = elu(v.x); v.y = elu(v.y); v.z = elu(v.z); v.w = elu(v.w);
            }
            *(float4*)(out + (size_t)n * HID + col) = v;
        }
    }
}

// ---------------- edge kernel: R7 structure + cp.async chunk-0 prefetch ----------------
static constexpr int AST = 136;
static constexpr int BST = 72;
static constexpr int DSTR = 68;
static constexpr int SM_AHI = 0;
static constexpr int SM_ALO = 34816;
static constexpr int SM_BHI = 69632;
static constexpr int SM_BLO = 88064;
static constexpr int SM_D   = 69632;
static constexpr int SM_WT  = 106496;
static constexpr int SM_B1  = 109056;
static constexpr int SM_B2  = 109568;
static constexpr int SM_ROW = 110080;
static constexpr int EDGE_SMEM_BYTES = 110592;

__global__ void __launch_bounds__(256, 2)
edge_hmma_kernel(const float* __restrict__ ew1, const float* __restrict__ eb1,
                 const float* __restrict__ eb2, int layer) {
    extern __shared__ char smem[];
    __nv_bfloat16* sAhi = (__nv_bfloat16*)(smem + SM_AHI);
    __nv_bfloat16* sAlo = (__nv_bfloat16*)(smem + SM_ALO);
    __nv_bfloat16* sBhi = (__nv_bfloat16*)(smem + SM_BHI);
    __nv_bfloat16* sBlo = (__nv_bfloat16*)(smem + SM_BLO);
    float* sD  = (float*)(smem + SM_D);
    float* sWT = (float*)(smem + SM_WT);
    float* sB1 = (float*)(smem + SM_B1);
    float* sB2 = (float*)(smem + SM_B2);
    int*   sRow = (int*)(smem + SM_ROW);

    int tid = threadIdx.x;
    int wid = tid >> 5;
    int e0 = blockIdx.x * 128;

    // prefetch B chunk 0 (hides behind staging + A-build)
    {
        const __nv_bfloat16* gh = g_Bh[layer];
        const __nv_bfloat16* gl = g_Bl[layer];
#pragma unroll
        for (int i = tid; i < 1024; i += 256) {
            int k = i >> 3, n8 = i & 7;
            cp16(sBhi + k * BST + n8 * 8, gh + k * HID + n8 * 8);
            cp16(sBlo + k * BST + n8 * 8, gl + k * HID + n8 * 8);
        }
        CP_COMMIT();
    }

    // stage tail weights, biases, sorted rows
    for (int i = tid; i < 5 * HID; i += 256) sWT[i] = ew1[(layer * 261 + 2 * HID) * HID + i];
    if (tid < HID) {
        sB1[tid] = eb1[layer * HID + tid];
        sB2[tid] = eb2[layer * HID + tid];
    }
    if (tid < 128) sRow[tid] = g_rowS[e0 + tid];
    __syncthreads();

    // A-build: elu(P1[row]+P2[col]+rad*w+ea@Wtail+b1) as bf16 hi/lo
    {
        int m = tid >> 1, hf = tid & 1;
        int e = e0 + m;
        int r = sRow[m], c = g_colS[e];
        float rad = g_radS[e];
        float4 ea = g_eaS[e];
        const float* p1r = g_P1 + (size_t)r * HID;
        const float* p2r = g_P2 + (size_t)c * HID;
#pragma unroll
        for (int q = 0; q < 16; q++) {
            int jb = hf * 64 + q * 4;
            float4 p1 = *(const float4*)(p1r + jb);
            float4 p2 = *(const float4*)(p2r + jb);
            float4 w0 = *(const float4*)(sWT + 0 * HID + jb);
            float4 w1 = *(const float4*)(sWT + 1 * HID + jb);
            float4 w2 = *(const float4*)(sWT + 2 * HID + jb);
            float4 w3 = *(const float4*)(sWT + 3 * HID + jb);
            float4 w4 = *(const float4*)(sWT + 4 * HID + jb);
            float4 bb = *(const float4*)(sB1 + jb);
            float o0 = elu(p1.x + p2.x + rad * w0.x + ea.x * w1.x + ea.y * w2.x + ea.z * w3.x + ea.w * w4.x + bb.x);
            float o1 = elu(p1.y + p2.y + rad * w0.y + ea.x * w1.y + ea.y * w2.y + ea.z * w3.y + ea.w * w4.y + bb.y);
            float o2 = elu(p1.z + p2.z + rad * w0.z + ea.x * w1.z + ea.y * w2.z + ea.z * w3.z + ea.w * w4.z + bb.z);
            float o3 = elu(p1.w + p2.w + rad * w0.w + ea.x * w1.w + ea.y * w2.w + ea.z * w3.w + ea.w * w4.w + bb.w);
            float h0f = __bfloat162float(__float2bfloat16(o0));
            float h1f = __bfloat162float(__float2bfloat16(o1));
            float h2f = __bfloat162float(__float2bfloat16(o2));
            float h3f = __bfloat162float(__float2bfloat16(o3));
            uint32_t* ph = (uint32_t*)(sAhi + m * AST + jb);
            uint32_t* pl = (uint32_t*)(sAlo + m * AST + jb);
            ph[0] = pack_bf16(h0f, h1f);
            ph[1] = pack_bf16(h2f, h3f);
            pl[0] = pack_bf16(o0 - h0f, o1 - h1f);
            pl[1] = pack_bf16(o2 - h2f, o3 - h3f);
        }
    }
    CP_WAIT0();
    __syncthreads();

    using namespace nvcuda::wmma;

#pragma unroll
    for (int nc = 0; nc < 2; nc++) {
        if (nc == 1) {
            // stage B chunk 1 (synchronous, as in R7)
            const __nv_bfloat16* gh = g_Bh[layer] + 64;
            const __nv_bfloat16* gl = g_Bl[layer] + 64;
#pragma unroll
            for (int i = tid; i < 1024; i += 256) {
                int k = i >> 3, n8 = i & 7;
                *(uint4*)(sBhi + k * BST + n8 * 8) = *(const uint4*)(gh + k * HID + n8 * 8);
                *(uint4*)(sBlo + k * BST + n8 * 8) = *(const uint4*)(gl + k * HID + n8 * 8);
            }
            __syncthreads();
        }

        // wmma: warp wid -> rows [wid*16, +16), all 64 chunk cols
        {
            int m0 = wid * 16;
            fragment<accumulator, 16, 16, 16, float> acc[4];
#pragma unroll
            for (int j = 0; j < 4; j++) fill_fragment(acc[j], 0.f);

#pragma unroll
            for (int k = 0; k < 8; k++) {
                fragment<matrix_a, 16, 16, 16, __nv_bfloat16, row_major> ah, al;
                load_matrix_sync(ah, sAhi + m0 * AST + k * 16, AST);
                load_matrix_sync(al, sAlo + m0 * AST + k * 16, AST);
#pragma unroll
                for (int nt = 0; nt < 4; nt++) {
                    fragment<matrix_b, 16, 16, 16, __nv_bfloat16, row_major> b;
                    load_matrix_sync(b, sBhi + (k * 16) * BST + nt * 16, BST);
                    mma_sync(acc[nt], ah, b, acc[nt]);
                    mma_sync(acc[nt], al, b, acc[nt]);
                }
            }
#pragma unroll
            for (int k = 0; k < 8; k++) {
                fragment<matrix_a, 16, 16, 16, __nv_bfloat16, row_major> ah;
                load_matrix_sync(ah, sAhi + m0 * AST + k * 16, AST);
#pragma unroll
                for (int nt = 0; nt < 4; nt++) {
                    fragment<matrix_b, 16, 16, 16, __nv_bfloat16, row_major> b;
                    load_matrix_sync(b, sBlo + (k * 16) * BST + nt * 16, BST);
                    mma_sync(acc[nt], ah, b, acc[nt]);
                }
            }

            __syncthreads();  // B chunk dead before D overwrites it
#pragma unroll
            for (int nt = 0; nt < 4; nt++)
                store_matrix_sync(sD + m0 * DSTR + nt * 16, acc[nt], DSTR, mem_row_major);
        }
        __syncthreads();

        // segmented scatter: eg = 8-edge group, ct = 4-col group
        {
            int ct = tid & 15, eg = tid >> 4;
            int jb = ct * 4;
            float b0 = sB2[nc * 64 + jb + 0];
            float b1v = sB2[nc * 64 + jb + 1];
            float b2v = sB2[nc * 64 + jb + 2];
            float b3v = sB2[nc * 64 + jb + 3];
            float r0 = 0.f, r1 = 0.f, r2 = 0.f, r3 = 0.f;
            int cur = sRow[eg * 8];
#pragma unroll
            for (int i = 0; i < 8; i++) {
                int m = eg * 8 + i;
                int rr = sRow[m];
                if (rr != cur) {
                    red4(g_agg + (size_t)cur * HID + nc * 64 + jb, r0, r1, r2, r3);
                    r0 = r1 = r2 = r3 = 0.f;
                    cur = rr;
                }
                const float* sd = sD + m * DSTR + jb;
                r0 += elu(sd[0] + b0);
                r1 += elu(sd[1] + b1v);
                r2 += elu(sd[2] + b2v);
                r3 += elu(sd[3] + b3v);
            }
            red4(g_agg + (size_t)cur * HID + nc * 64 + jb, r0, r1, r2, r3);
        }
        __syncthreads();  // D dead before next chunk stages B
    }
}

// ---------------- final head ----------------
__global__ void final_kernel(const float* __restrict__ label,
                             const float* __restrict__ eps,
                             const float* __restrict__ mu_w, const float* __restrict__ mu_b,
                             const float* __restrict__ var_w, const float* __restrict__ var_b,
                             float* __restrict__ out) {
    int idx = blockIdx.x * 256 + threadIdx.x;
    if (idx >= NN * LATD) return;
    int n = idx >> 6, l = idx & 63;
    float am = mu_b[l], av = var_b[l];
    const float* hrow = g_h0buf + n * HID;
#pragma unroll 4
    for (int k = 0; k < HID; k++) {
        float hv = hrow[k];
        am += hv * mu_w[k * LATD + l];
        av += hv * var_w[k * LATD + l];
    }
#pragma unroll
    for (int c = 0; c < 7; c++) {
        float lv = label[n * 7 + c];
        am += lv * mu_w[(HID + c) * LATD + l];
        av += lv * var_w[(HID + c) * LATD + l];
    }
    out[idx] = am + 0.01f * eps[idx] * __expf(0.5f * av);
}

// ---------------- launch ----------------
extern "C" void kernel_launch(void* const* d_in, const int* in_sizes, int n_in,
                              void* d_out, int out_size) {
    const float* h0        = (const float*)d_in[0];
    const float* label     = (const float*)d_in[1];
    const float* x         = (const float*)d_in[2];
    const float* edge_attr = (const float*)d_in[3];
    const float* eps       = (const float*)d_in[4];
    const float* emb_w     = (const float*)d_in[5];
    const float* emb_b     = (const float*)d_in[6];
    const float* ew1       = (const float*)d_in[7];
    const float* eb1       = (const float*)d_in[8];
    const float* ew2       = (const float*)d_in[9];
    const float* eb2       = (const float*)d_in[10];
    const float* nw1       = (const float*)d_in[11];
    const float* nb1       = (const float*)d_in[12];
    const float* nw2       = (const float*)d_in[13];
    const float* nb2       = (const float*)d_in[14];
    const float* mu_w      = (const float*)d_in[15];
    const float* mu_b      = (const float*)d_in[16];
    const float* var_w     = (const float*)d_in[17];
    const float* var_b     = (const float*)d_in[18];
    const int*   edges     = (const int*)d_in[19];
    const int* rowp = edges;
    const int* colp = edges + NE;
    float* out = (float*)d_out;

    cudaFuncSetAttribute(edge_hmma_kernel, cudaFuncAttributeMaxDynamicSharedMemorySize, EDGE_SMEM_BYTES);
    cudaFuncSetAttribute(gemm_wmma_kernel, cudaFuncAttributeMaxDynamicSharedMemorySize, GEMM_SMEM);

    const int GGRID = (NN + 127) / 128;   // 391

    embed_kernel<<<(NN * HID + 255) / 256, 256>>>(h0, emb_w, emb_b);
    w2prep_kernel<<<(2 * HID * HID + 255) / 256, 256>>>(ew2);
    prep_split_kernel<<<(163840 + 255) / 256, 256>>>(ew1, nw1, nw2);

    // counting sort of edges by source node (once per launch)
    sort_zero_kernel<<<(NN + 255) / 256, 256>>>();
    sort_hist_kernel<<<(NE + 255) / 256, 256>>>(rowp);
    sort_scan1_kernel<<<NB_SCAN, 512>>>();
    sort_scan2_kernel<<<1, 32>>>();
    sort_scan3_kernel<<<(NN + 255) / 256, 256>>>();
    sort_scatter_kernel<<<(NE + 255) / 256, 256>>>(rowp, colp, x, edge_attr);

    float *h0p, *h1p, *p1p, *p2p, *aggp, *nfp;
    cudaGetSymbolAddress((void**)&h0p, g_h0buf);
    cudaGetSymbolAddress((void**)&h1p, g_h1buf);
    cudaGetSymbolAddress((void**)&p1p, g_P1);
    cudaGetSymbolAddress((void**)&p2p, g_P2);
    cudaGetSymbolAddress((void**)&aggp, g_agg);
    cudaGetSymbolAddress((void**)&nfp, g_nf);
    __nv_bfloat16 *e1h, *e1l, *n1h, *n1l, *n2h, *n2l;
    cudaGetSymbolAddress((void**)&e1h, g_E1h);
    cudaGetSymbolAddress((void**)&e1l, g_E1l);
    cudaGetSymbolAddress((void**)&n1h, g_N1h);
    cudaGetSymbolAddress((void**)&n1l, g_N1l);
    cudaGetSymbolAddress((void**)&n2h, g_N2h);
    cudaGetSymbolAddress((void**)&n2l, g_N2l);

    for (int layer = 0; layer < 2; layer++) {
        float* hsrc_p = (layer == 0) ? h0p : h1p;
        float* hdst   = (layer == 0) ? h1p : h0p;

        zero_agg_kernel<<<(NN * HID / 4 + 255) / 256, 256>>>();

        // P1 and P2 in one launch (gridDim.y = 2)
        gemm_wmma_kernel<<<dim3(GGRID, 2), 256, GEMM_SMEM>>>(
            hsrc_p, nullptr, 2,
            e1h + (size_t)layer * 2 * HID * HID, e1l + (size_t)layer * 2 * HID * HID,
            nullptr, p1p, 0,
            e1h + ((size_t)layer * 2 + 1) * HID * HID,
            e1l + ((size_t)layer * 2 + 1) * HID * HID, p2p);

        edge_hmma_kernel<<<NE / 128, 256, EDGE_SMEM_BYTES>>>(ew1, eb1, eb2, layer);

        // node GEMM1: nf = elu([h|agg] @ N1 + nb1)
        gemm_wmma_kernel<<<dim3(GGRID, 1), 256, GEMM_SMEM>>>(
            hsrc_p, aggp, 4,
            n1h + (size_t)layer * 2 * HID * HID, n1l + (size_t)layer * 2 * HID * HID,
            nb1 + layer * HID, nfp, 1, nullptr, nullptr, nullptr);
        // node GEMM2: hdst = nf @ N2 + nb2
        gemm_wmma_kernel<<<dim3(GGRID, 1), 256, GEMM_SMEM>>>(
            nfp, nullptr, 2,
            n2h + (size_t)layer * HID * HID, n2l + (size_t)layer * HID * HID,
            nb2 + layer * HID, hdst, 0, nullptr, nullptr, nullptr);
    }

    final_kernel<<<(NN * LATD + 255) / 256, 256>>>(label, eps, mu_w, mu_b,
                                                   var_w, var_b, out);
}

// round 11
// speedup vs baseline: 1.5032x; 1.3011x over previous
#include <cuda_runtime.h>
#include <cuda_bf16.h>
#include <cuda_fp16.h>
#include <mma.h>
#include <cstdint>

#define NN 50000
#define NE 800000
#define HID 128
#define LATD 64
#define IN_NODE 11
#define IN_EDGE 4
#define NB_SCAN 98   // ceil(50000/512)

// ---------------- device scratch ----------------
__device__ float g_h0buf[NN * HID];
__device__ float g_h1buf[NN * HID];
__device__ float g_agg[NN * HID];
__device__ float g_P1[NN * HID];
__device__ float g_P2[NN * HID];
__device__ float g_nf[NN * HID];
// counting-sort scratch
__device__ int g_cnt[NN];
__device__ int g_off[NB_SCAN * 512];
__device__ int g_cur[NN];
__device__ int g_blksum[NB_SCAN];
__device__ int g_blkoff[NB_SCAN];
// permuted (row-sorted) edge arrays
__device__ int   g_rowS[NE];
__device__ int   g_colS[NE];
__device__ float g_radS[NE];
__device__ float4 g_eaS[NE];
// edge W2 as fp16 [K][N] per layer (single-pass edge GEMM)
__device__ __half g_Wf16[2][HID * HID];
// bf16 hi/lo weight splits (pre/node GEMMs)
__device__ __nv_bfloat16 g_E1h[2][2][HID * HID];      // ew1 rows 0..255 as two [128][128]
__device__ __nv_bfloat16 g_E1l[2][2][HID * HID];
__device__ __nv_bfloat16 g_N1h[2][2 * HID * HID];     // [wsum ; W1b] [256][128]
__device__ __nv_bfloat16 g_N1l[2][2 * HID * HID];
__device__ __nv_bfloat16 g_N2h[2][HID * HID];         // nw2 [128][128]
__device__ __nv_bfloat16 g_N2l[2][HID * HID];

__device__ __forceinline__ float elu(float v) {
    return v > 0.f ? v : (__expf(v) - 1.f);
}

__device__ __forceinline__ void red4(float* p, float a, float b, float c, float d) {
    asm volatile("red.global.add.v4.f32 [%0], {%1,%2,%3,%4};"
                 :: "l"(p), "f"(a), "f"(b), "f"(c), "f"(d) : "memory");
}

__device__ __forceinline__ uint32_t pack_bf16(float e0, float e1) {
    uint32_t r;
    asm("cvt.rn.bf16x2.f32 %0, %1, %2;" : "=r"(r) : "f"(e1), "f"(e0));
    return r;
}

// cp.async helpers (16B)
__device__ __forceinline__ void cp16(void* smem_dst, const void* gsrc) {
    uint32_t d = (uint32_t)__cvta_generic_to_shared(smem_dst);
    asm volatile("cp.async.ca.shared.global [%0], [%1], 16;" :: "r"(d), "l"(gsrc) : "memory");
}
#define CP_COMMIT() asm volatile("cp.async.commit_group;" ::: "memory")
#define CP_WAIT0()  asm volatile("cp.async.wait_group 0;" ::: "memory")

// ---------------- small kernels ----------------
__global__ void embed_kernel(const float* __restrict__ h0,
                             const float* __restrict__ emb_w,
                             const float* __restrict__ emb_b) {
    int idx = blockIdx.x * 256 + threadIdx.x;
    if (idx >= NN * HID) return;
    int n = idx >> 7, j = idx & 127;
    float acc = emb_b[j];
#pragma unroll
    for (int k = 0; k < IN_NODE; k++)
        acc += h0[n * IN_NODE + k] * emb_w[k * HID + j];
    g_h0buf[idx] = acc;
}

__global__ void zero_agg_kernel() {
    int i = blockIdx.x * 256 + threadIdx.x;
    if (i < NN * HID / 4)
        ((float4*)g_agg)[i] = make_float4(0.f, 0.f, 0.f, 0.f);
}

// edge W2 -> fp16 [K][N]
__global__ void w2prep_kernel(const float* __restrict__ ew2) {
    int idx = blockIdx.x * 256 + threadIdx.x;
    if (idx >= 2 * HID * HID) return;
    int layer = idx >> 14;
    int rem = idx & 16383;
    g_Wf16[layer][rem] = __float2half(ew2[layer * HID * HID + rem]);
}

// split ew1 (rows 0..255), node W1 (wsum-folded), node W2 into bf16 hi/lo
__global__ void prep_split_kernel(const float* __restrict__ ew1,
                                  const float* __restrict__ nw1,
                                  const float* __restrict__ nw2) {
    int idx = blockIdx.x * 256 + threadIdx.x;
    if (idx >= 163840) return;
    float v;
    __nv_bfloat16 *dh, *dl;
    if (idx < 65536) {
        int l = idx >> 15, rest = idx & 32767;
        int y = rest >> 14, r2 = rest & 16383;
        v = ew1[(l * 261 + y * 128 + (r2 >> 7)) * 128 + (r2 & 127)];
        dh = &g_E1h[l][y][r2];
        dl = &g_E1l[l][y][r2];
    } else if (idx < 131072) {
        int t = idx - 65536;
        int l = t >> 15, rest = t & 32767;
        int k = rest >> 7, j = rest & 127;
        if (k < 128)
            v = nw1[(l * 384 + k) * 128 + j] + nw1[(l * 384 + 256 + k) * 128 + j];
        else
            v = nw1[(l * 384 + 128 + (k - 128)) * 128 + j];
        dh = &g_N1h[l][rest];
        dl = &g_N1l[l][rest];
    } else {
        int t = idx - 131072;
        int l = t >> 14, rest = t & 16383;
        v = nw2[l * 16384 + rest];
        dh = &g_N2h[l][rest];
        dl = &g_N2l[l][rest];
    }
    __nv_bfloat16 hb = __float2bfloat16(v);
    *dh = hb;
    *dl = __float2bfloat16(v - __bfloat162float(hb));
}

// ---------------- counting sort of edges by row ----------------
__global__ void sort_zero_kernel() {
    int i = blockIdx.x * 256 + threadIdx.x;
    if (i < NN) g_cnt[i] = 0;
}

__global__ void sort_hist_kernel(const int* __restrict__ row) {
    int e = blockIdx.x * 256 + threadIdx.x;
    if (e < NE) atomicAdd(&g_cnt[row[e]], 1);
}

__global__ void sort_scan1_kernel() {
    __shared__ int buf[512];
    int t = threadIdx.x;
    int i = blockIdx.x * 512 + t;
    int v = (i < NN) ? g_cnt[i] : 0;
    buf[t] = v;
    __syncthreads();
#pragma unroll
    for (int d = 1; d < 512; d <<= 1) {
        int x = (t >= d) ? buf[t - d] : 0;
        __syncthreads();
        buf[t] += x;
        __syncthreads();
    }
    g_off[i] = buf[t] - v;
    if (t == 511) g_blksum[blockIdx.x] = buf[511];
}

__global__ void sort_scan2_kernel() {
    if (threadIdx.x == 0) {
        int s = 0;
        for (int k = 0; k < NB_SCAN; k++) {
            g_blkoff[k] = s;
            s += g_blksum[k];
        }
    }
}

__global__ void sort_scan3_kernel() {
    int i = blockIdx.x * 256 + threadIdx.x;
    if (i < NN) {
        int o = g_off[i] + g_blkoff[i >> 9];
        g_off[i] = o;
        g_cur[i] = o;
    }
}

__global__ void sort_scatter_kernel(const int* __restrict__ row,
                                    const int* __restrict__ col,
                                    const float* __restrict__ x,
                                    const float* __restrict__ edge_attr) {
    int e = blockIdx.x * 256 + threadIdx.x;
    if (e >= NE) return;
    int r = row[e], c = col[e];
    float dx = x[r * 3 + 0] - x[c * 3 + 0];
    float dy = x[r * 3 + 1] - x[c * 3 + 1];
    float dz = x[r * 3 + 2] - x[c * 3 + 2];
    float rad = dx * dx + dy * dy + dz * dz;
    int pos = atomicAdd(&g_cur[r], 1);
    g_rowS[pos] = r;
    g_colS[pos] = c;
    g_radS[pos] = rad;
    g_eaS[pos] = *(const float4*)(edge_attr + (size_t)e * 4);
}

// ---------------- generic dense GEMM (bf16 3-pass, cp.async): unchanged from R10 ----------------
static constexpr int GA_ST = 72;
static constexpr int GB_ST = 136;
static constexpr int GD_ST = 132;
static constexpr int G_SAH = 0;
static constexpr int G_SAL = 18432;
static constexpr int G_SBH = 36864;
static constexpr int G_SBL = 54272;
static constexpr int GEMM_SMEM = 71680;

__global__ void __launch_bounds__(256, 2)
gemm_wmma_kernel(const float* __restrict__ A0, const float* __restrict__ A1,
                 int k64,
                 const __nv_bfloat16* __restrict__ Bh,
                 const __nv_bfloat16* __restrict__ Bl,
                 const float* __restrict__ bias,
                 float* __restrict__ out, int do_elu,
                 const __nv_bfloat16* Bh2, const __nv_bfloat16* Bl2, float* out2) {
    extern __shared__ char smem[];
    __nv_bfloat16* sAh = (__nv_bfloat16*)(smem + G_SAH);
    __nv_bfloat16* sAl = (__nv_bfloat16*)(smem + G_SAL);
    __nv_bfloat16* sBh = (__nv_bfloat16*)(smem + G_SBH);
    __nv_bfloat16* sBl = (__nv_bfloat16*)(smem + G_SBL);
    float* sD = (float*)smem;

    if (blockIdx.y == 1) { Bh = Bh2; Bl = Bl2; out = out2; }

    int tid = threadIdx.x;
    int wid = tid >> 5;
    int n0 = blockIdx.x * 128;
    int r = tid >> 1, hf = tid & 1;
    int n = n0 + r;

    using namespace nvcuda::wmma;
    fragment<accumulator, 16, 16, 16, float> acc[8];
#pragma unroll
    for (int j = 0; j < 8; j++) fill_fragment(acc[j], 0.f);

    for (int c = 0; c < k64; c++) {
        {
#pragma unroll
            for (int it = 0; it < 4; it++) {
                int i = tid + it * 256;
                int kb = i >> 4, u = i & 15;
                cp16(sBh + kb * GB_ST + u * 8, Bh + (size_t)(c * 64 + kb) * HID + u * 8);
                cp16(sBl + kb * GB_ST + u * 8, Bl + (size_t)(c * 64 + kb) * HID + u * 8);
            }
            CP_COMMIT();
        }
        {
            const float* src = (c < 2) ? A0 : A1;
            int kbase = (c & 1) * 64;
            if (n < NN) {
#pragma unroll
                for (int q = 0; q < 8; q++) {
                    int col = hf * 32 + q * 4;
                    float4 v = *(const float4*)(src + (size_t)n * HID + kbase + col);
                    float h0f = __bfloat162float(__float2bfloat16(v.x));
                    float h1f = __bfloat162float(__float2bfloat16(v.y));
                    float h2f = __bfloat162float(__float2bfloat16(v.z));
                    float h3f = __bfloat162float(__float2bfloat16(v.w));
                    uint32_t* ph = (uint32_t*)(sAh + r * GA_ST + col);
                    uint32_t* pl = (uint32_t*)(sAl + r * GA_ST + col);
                    ph[0] = pack_bf16(h0f, h1f);
                    ph[1] = pack_bf16(h2f, h3f);
                    pl[0] = pack_bf16(v.x - h0f, v.y - h1f);
                    pl[1] = pack_bf16(v.z - h2f, v.w - h3f);
                }
            } else {
#pragma unroll
                for (int q = 0; q < 8; q++) {
                    int col = hf * 32 + q * 4;
                    uint32_t* ph = (uint32_t*)(sAh + r * GA_ST + col);
                    uint32_t* pl = (uint32_t*)(sAl + r * GA_ST + col);
                    ph[0] = 0; ph[1] = 0; pl[0] = 0; pl[1] = 0;
                }
            }
        }
        CP_WAIT0();
        __syncthreads();

        {
            int m0 = wid * 16;
#pragma unroll
            for (int kf = 0; kf < 4; kf++) {
                fragment<matrix_a, 16, 16, 16, __nv_bfloat16, row_major> ah, al;
                load_matrix_sync(ah, sAh + m0 * GA_ST + kf * 16, GA_ST);
                load_matrix_sync(al, sAl + m0 * GA_ST + kf * 16, GA_ST);
#pragma unroll
                for (int nf = 0; nf < 8; nf++) {
                    fragment<matrix_b, 16, 16, 16, __nv_bfloat16, row_major> b;
                    load_matrix_sync(b, sBh + (kf * 16) * GB_ST + nf * 16, GB_ST);
                    mma_sync(acc[nf], ah, b, acc[nf]);
                    mma_sync(acc[nf], al, b, acc[nf]);
                }
            }
#pragma unroll
            for (int kf = 0; kf < 4; kf++) {
                fragment<matrix_a, 16, 16, 16, __nv_bfloat16, row_major> ah;
                load_matrix_sync(ah, sAh + m0 * GA_ST + kf * 16, GA_ST);
#pragma unroll
                for (int nf = 0; nf < 8; nf++) {
                    fragment<matrix_b, 16, 16, 16, __nv_bfloat16, row_major> b;
                    load_matrix_sync(b, sBl + (kf * 16) * GB_ST + nf * 16, GB_ST);
                    mma_sync(acc[nf], ah, b, acc[nf]);
                }
            }
        }
        __syncthreads();
    }

    {
        int m0 = wid * 16;
#pragma unroll
        for (int nf = 0; nf < 8; nf++)
            store_matrix_sync(sD + m0 * GD_ST + nf * 16, acc[nf], GD_ST, mem_row_major);
    }
    __syncthreads();

    if (n < NN) {
#pragma unroll
        for (int q = 0; q < 16; q++) {
            int col = hf * 64 + q * 4;
            float4 v = *(const float4*)(sD + r * GD_ST + col);
            if (bias) {
                v.x += bias[col + 0];
                v.y += bias[col + 1];
                v.z += bias[col + 2];
                v.w += bias[col + 3];
            }
            if (do_elu) {
                v.x = elu(v.x); v.y = elu(v.y); v.z = elu(v.z); v.w = elu(v.w);
            }
            *(float4*)(out + (size_t)n * HID + col) = v;
        }
    }
}

// ---------------- edge kernel: single-pass fp16 MMA, full-N resident B ----------------
static constexpr int AST = 136;   // fp16 stride
static constexpr int DSTR = 132;  // f32 stride, D (unions A+B after MMA)
static constexpr int SM_A  = 0;        // 128*136*2 = 34816
static constexpr int SM_B  = 34816;    // 34816 -> 69632
static constexpr int SM_WT = 69632;    // 5*128*4 = 2560
static constexpr int SM_B1 = 72192;    // 512
static constexpr int SM_B2 = 72704;    // 512
static constexpr int SM_ROW = 73216;   // 512
static constexpr int EDGE_SMEM_BYTES = 73728;

__global__ void __launch_bounds__(256, 2)
edge_hmma_kernel(const float* __restrict__ ew1, const float* __restrict__ eb1,
                 const float* __restrict__ eb2, int layer) {
    extern __shared__ char smem[];
    __half* sA = (__half*)(smem + SM_A);
    __half* sB = (__half*)(smem + SM_B);
    float* sD  = (float*)smem;
    float* sWT = (float*)(smem + SM_WT);
    float* sB1 = (float*)(smem + SM_B1);
    float* sB2 = (float*)(smem + SM_B2);
    int*   sRow = (int*)(smem + SM_ROW);

    int tid = threadIdx.x;
    int wid = tid >> 5;
    int e0 = blockIdx.x * 128;

    // prefetch full B [128k][128n] fp16 via cp.async (hides behind A-build)
    {
        const __half* gW = g_Wf16[layer];
#pragma unroll
        for (int it = 0; it < 8; it++) {
            int i = tid + it * 256;
            int k = i >> 4, u = i & 15;
            cp16(sB + k * AST + u * 8, gW + k * HID + u * 8);
        }
        CP_COMMIT();
    }

    // stage tail weights, biases, sorted rows
    for (int i = tid; i < 5 * HID; i += 256) sWT[i] = ew1[(layer * 261 + 2 * HID) * HID + i];
    if (tid < HID) {
        sB1[tid] = eb1[layer * HID + tid];
        sB2[tid] = eb2[layer * HID + tid];
    }
    if (tid < 128) sRow[tid] = g_rowS[e0 + tid];
    __syncthreads();

    // A-build: elu(P1[row]+P2[col]+rad*w+ea@Wtail+b1) -> fp16
    {
        int m = tid >> 1, hf = tid & 1;
        int e = e0 + m;
        int r = sRow[m], c = g_colS[e];
        float rad = g_radS[e];
        float4 ea = g_eaS[e];
        const float* p1r = g_P1 + (size_t)r * HID;
        const float* p2r = g_P2 + (size_t)c * HID;
#pragma unroll
        for (int q = 0; q < 16; q++) {
            int jb = hf * 64 + q * 4;
            float4 p1 = *(const float4*)(p1r + jb);
            float4 p2 = *(const float4*)(p2r + jb);
            float4 w0 = *(const float4*)(sWT + 0 * HID + jb);
            float4 w1 = *(const float4*)(sWT + 1 * HID + jb);
            float4 w2 = *(const float4*)(sWT + 2 * HID + jb);
            float4 w3 = *(const float4*)(sWT + 3 * HID + jb);
            float4 w4 = *(const float4*)(sWT + 4 * HID + jb);
            float4 bb = *(const float4*)(sB1 + jb);
            float o0 = elu(p1.x + p2.x + rad * w0.x + ea.x * w1.x + ea.y * w2.x + ea.z * w3.x + ea.w * w4.x + bb.x);
            float o1 = elu(p1.y + p2.y + rad * w0.y + ea.x * w1.y + ea.y * w2.y + ea.z * w3.y + ea.w * w4.y + bb.y);
            float o2 = elu(p1.z + p2.z + rad * w0.z + ea.x * w1.z + ea.y * w2.z + ea.z * w3.z + ea.w * w4.z + bb.z);
            float o3 = elu(p1.w + p2.w + rad * w0.w + ea.x * w1.w + ea.y * w2.w + ea.z * w3.w + ea.w * w4.w + bb.w);
            __half2* pa = (__half2*)(sA + m * AST + jb);
            pa[0] = __floats2half2_rn(o0, o1);
            pa[1] = __floats2half2_rn(o2, o3);
        }
    }
    CP_WAIT0();
    __syncthreads();

    // single-pass fp16 MMA: warp wid -> rows [wid*16,+16), all 128 cols
    using namespace nvcuda::wmma;
    {
        int m0 = wid * 16;
        fragment<accumulator, 16, 16, 16, float> acc[8];
#pragma unroll
        for (int j = 0; j < 8; j++) fill_fragment(acc[j], 0.f);

#pragma unroll
        for (int k = 0; k < 8; k++) {
            fragment<matrix_a, 16, 16, 16, __half, row_major> a;
            load_matrix_sync(a, sA + m0 * AST + k * 16, AST);
#pragma unroll
            for (int nf = 0; nf < 8; nf++) {
                fragment<matrix_b, 16, 16, 16, __half, row_major> b;
                load_matrix_sync(b, sB + (k * 16) * AST + nf * 16, AST);
                mma_sync(acc[nf], a, b, acc[nf]);
            }
        }

        __syncthreads();   // A and B fully dead -> D may overwrite
#pragma unroll
        for (int nf = 0; nf < 8; nf++)
            store_matrix_sync(sD + m0 * DSTR + nf * 16, acc[nf], DSTR, mem_row_major);
    }
    __syncthreads();

    // single merged scatter: eg = 8-edge group, ct = 8-col group
    {
        int ct = tid & 15, eg = tid >> 4;
        int jb = ct * 8;
        float b2v[8];
#pragma unroll
        for (int k = 0; k < 8; k++) b2v[k] = sB2[jb + k];
        float run[8];
#pragma unroll
        for (int k = 0; k < 8; k++) run[k] = 0.f;
        int cur = sRow[eg * 8];
#pragma unroll
        for (int i = 0; i < 8; i++) {
            int m = eg * 8 + i;
            int rr = sRow[m];
            if (rr != cur) {
                float* dst = g_agg + (size_t)cur * HID + jb;
                red4(dst, run[0], run[1], run[2], run[3]);
                red4(dst + 4, run[4], run[5], run[6], run[7]);
#pragma unroll
                for (int k = 0; k < 8; k++) run[k] = 0.f;
                cur = rr;
            }
            const float* sd = sD + m * DSTR + jb;
#pragma unroll
            for (int k = 0; k < 8; k++) run[k] += elu(sd[k] + b2v[k]);
        }
        float* dst = g_agg + (size_t)cur * HID + jb;
        red4(dst, run[0], run[1], run[2], run[3]);
        red4(dst + 4, run[4], run[5], run[6], run[7]);
    }
}

// ---------------- final head ----------------
__global__ void final_kernel(const float* __restrict__ label,
                             const float* __restrict__ eps,
                             const float* __restrict__ mu_w, const float* __restrict__ mu_b,
                             const float* __restrict__ var_w, const float* __restrict__ var_b,
                             float* __restrict__ out) {
    int idx = blockIdx.x * 256 + threadIdx.x;
    if (idx >= NN * LATD) return;
    int n = idx >> 6, l = idx & 63;
    float am = mu_b[l], av = var_b[l];
    const float* hrow = g_h0buf + n * HID;
#pragma unroll 4
    for (int k = 0; k < HID; k++) {
        float hv = hrow[k];
        am += hv * mu_w[k * LATD + l];
        av += hv * var_w[k * LATD + l];
    }
#pragma unroll
    for (int c = 0; c < 7; c++) {
        float lv = label[n * 7 + c];
        am += lv * mu_w[(HID + c) * LATD + l];
        av += lv * var_w[(HID + c) * LATD + l];
    }
    out[idx] = am + 0.01f * eps[idx] * __expf(0.5f * av);
}

// ---------------- launch ----------------
extern "C" void kernel_launch(void* const* d_in, const int* in_sizes, int n_in,
                              void* d_out, int out_size) {
    const float* h0        = (const float*)d_in[0];
    const float* label     = (const float*)d_in[1];
    const float* x         = (const float*)d_in[2];
    const float* edge_attr = (const float*)d_in[3];
    const float* eps       = (const float*)d_in[4];
    const float* emb_w     = (const float*)d_in[5];
    const float* emb_b     = (const float*)d_in[6];
    const float* ew1       = (const float*)d_in[7];
    const float* eb1       = (const float*)d_in[8];
    const float* ew2       = (const float*)d_in[9];
    const float* eb2       = (const float*)d_in[10];
    const float* nw1       = (const float*)d_in[11];
    const float* nb1       = (const float*)d_in[12];
    const float* nw2       = (const float*)d_in[13];
    const float* nb2       = (const float*)d_in[14];
    const float* mu_w      = (const float*)d_in[15];
    const float* mu_b      = (const float*)d_in[16];
    const float* var_w     = (const float*)d_in[17];
    const float* var_b     = (const float*)d_in[18];
    const int*   edges     = (const int*)d_in[19];
    const int* rowp = edges;
    const int* colp = edges + NE;
    float* out = (float*)d_out;

    cudaFuncSetAttribute(edge_hmma_kernel, cudaFuncAttributeMaxDynamicSharedMemorySize, EDGE_SMEM_BYTES);
    cudaFuncSetAttribute(gemm_wmma_kernel, cudaFuncAttributeMaxDynamicSharedMemorySize, GEMM_SMEM);

    const int GGRID = (NN + 127) / 128;   // 391

    embed_kernel<<<(NN * HID + 255) / 256, 256>>>(h0, emb_w, emb_b);
    w2prep_kernel<<<(2 * HID * HID + 255) / 256, 256>>>(ew2);
    prep_split_kernel<<<(163840 + 255) / 256, 256>>>(ew1, nw1, nw2);

    // counting sort of edges by source node (once per launch)
    sort_zero_kernel<<<(NN + 255) / 256, 256>>>();
    sort_hist_kernel<<<(NE + 255) / 256, 256>>>(rowp);
    sort_scan1_kernel<<<NB_SCAN, 512>>>();
    sort_scan2_kernel<<<1, 32>>>();
    sort_scan3_kernel<<<(NN + 255) / 256, 256>>>();
    sort_scatter_kernel<<<(NE + 255) / 256, 256>>>(rowp, colp, x, edge_attr);

    float *h0p, *h1p, *p1p, *p2p, *aggp, *nfp;
    cudaGetSymbolAddress((void**)&h0p, g_h0buf);
    cudaGetSymbolAddress((void**)&h1p, g_h1buf);
    cudaGetSymbolAddress((void**)&p1p, g_P1);
    cudaGetSymbolAddress((void**)&p2p, g_P2);
    cudaGetSymbolAddress((void**)&aggp, g_agg);
    cudaGetSymbolAddress((void**)&nfp, g_nf);
    __nv_bfloat16 *e1h, *e1l, *n1h, *n1l, *n2h, *n2l;
    cudaGetSymbolAddress((void**)&e1h, g_E1h);
    cudaGetSymbolAddress((void**)&e1l, g_E1l);
    cudaGetSymbolAddress((void**)&n1h, g_N1h);
    cudaGetSymbolAddress((void**)&n1l, g_N1l);
    cudaGetSymbolAddress((void**)&n2h, g_N2h);
    cudaGetSymbolAddress((void**)&n2l, g_N2l);

    for (int layer = 0; layer < 2; layer++) {
        float* hsrc_p = (layer == 0) ? h0p : h1p;
        float* hdst   = (layer == 0) ? h1p : h0p;

        zero_agg_kernel<<<(NN * HID / 4 + 255) / 256, 256>>>();

        // P1 and P2 in one launch (gridDim.y = 2)
        gemm_wmma_kernel<<<dim3(GGRID, 2), 256, GEMM_SMEM>>>(
            hsrc_p, nullptr, 2,
            e1h + (size_t)layer * 2 * HID * HID, e1l + (size_t)layer * 2 * HID * HID,
            nullptr, p1p, 0,
            e1h + ((size_t)layer * 2 + 1) * HID * HID,
            e1l + ((size_t)layer * 2 + 1) * HID * HID, p2p);

        edge_hmma_kernel<<<NE / 128, 256, EDGE_SMEM_BYTES>>>(ew1, eb1, eb2, layer);

        // node GEMM1: nf = elu([h|agg] @ N1 + nb1)
        gemm_wmma_kernel<<<dim3(GGRID, 1), 256, GEMM_SMEM>>>(
            hsrc_p, aggp, 4,
            n1h + (size_t)layer * 2 * HID * HID, n1l + (size_t)layer * 2 * HID * HID,
            nb1 + layer * HID, nfp, 1, nullptr, nullptr, nullptr);
        // node GEMM2: hdst = nf @ N2 + nb2
        gemm_wmma_kernel<<<dim3(GGRID, 1), 256, GEMM_SMEM>>>(
            nfp, nullptr, 2,
            n2h + (size_t)layer * HID * HID, n2l + (size_t)layer * HID * HID,
            nb2 + layer * HID, hdst, 0, nullptr, nullptr, nullptr);
    }

    final_kernel<<<(NN * LATD + 255) / 256, 256>>>(label, eps, mu_w, mu_b,
                                                   var_w, var_b, out);
}